// round 4
// baseline (speedup 1.0000x reference)
#include <cuda_runtime.h>
#include <cstdint>
#include <math.h>

// ---------------------------------------------------------------------------
// SIM3Policy fused: B=8, M=16384, E=2, C=128, H=128, Vin=136.
// out = [offsets (B,M,6) | gripper (B,2) | ac (B,14)] flattened fp32.
// ---------------------------------------------------------------------------

#define EPSN 1e-6f
typedef unsigned long long ull;

#define NB   8
#define NM   16384
#define NH   128
#define TSP  64          // points per CTA tile
#define KC   16          // k chunk for z staging
#define XROW 192         // floats per intermediate row (3*64)
#define GRIP_OFF (NB*NM*6)
#define AC_OFF   (GRIP_OFF + NB*2)

// -------------------- device scratch ---------------------------------------
__device__ float g_WT[4][NH*NH];     // W1x(:, :128)^T, W1x_d^T, W2x^T, W2x_d^T  [k][o]
__device__ float g_bias1[NB*NH*3];   // z_state contribution to layer-1 q
__device__ float g_s2v1[NB*NH];
__device__ float g_zstate[NB*8*3];
__device__ float g_zposn[NB*2*3];
__device__ float g_grip[NB*2];
__device__ int   g_closest[NB*2];

// -------------------- helpers ----------------------------------------------
__device__ __forceinline__ ull bc2(float x){
    ull r; asm("mov.b64 %0, {%1, %1};" : "=l"(r) : "r"(__float_as_uint(x))); return r;
}
__device__ __forceinline__ void fma2(ull& a, ull x, ull y){
    asm("fma.rn.f32x2 %0, %1, %2, %0;" : "+l"(a) : "l"(x), "l"(y));
}
union F2U { float2 f; ull u; };
__device__ __forceinline__ float2 u2f(ull v){ F2U t; t.u = v; return t.f; }
__device__ __forceinline__ ull f2u(float a, float b){ F2U t; t.f = make_float2(a,b); return t.u; }

__device__ __forceinline__ void cp16(float* dst, const float* src){
    unsigned d = (unsigned)__cvta_generic_to_shared(dst);
    asm volatile("cp.async.cg.shared.global [%0], [%1], 16;" :: "r"(d), "l"(src));
}
__device__ __forceinline__ void cpcommit(){ asm volatile("cp.async.commit_group;"); }
__device__ __forceinline__ void cpwait0(){ asm volatile("cp.async.wait_group 0;"); }

// GEMM over the X intermediate buffer (128 x XROW, xor-swizzled rows).
__device__ __forceinline__ void gemm_x(const float* __restrict__ Wt, const float* Xs,
                                       ull acc[8][6], int tr, int tc)
{
    const int jb0 = tc, jb1 = 16 + tc, jb2 = 32 + tc;
    #pragma unroll 4
    for (int k = 0; k < NH; k++){
        const int key = (k >> 3) & 7;
        const float4 a0 = __ldg((const float4*)(Wt + k*NH + tr*8));
        const float4 a1 = __ldg((const float4*)(Wt + k*NH + tr*8 + 4));
        ull A0=bc2(a0.x),A1=bc2(a0.y),A2=bc2(a0.z),A3=bc2(a0.w);
        ull A4=bc2(a1.x),A5=bc2(a1.y),A6=bc2(a1.z),A7=bc2(a1.w);
        const float* xr = Xs + k*XROW;
        ulonglong2 b0 = *(const ulonglong2*)(xr + ((jb0 ^ key) << 2));
        ulonglong2 b1 = *(const ulonglong2*)(xr + ((jb1 ^ key) << 2));
        ulonglong2 b2 = *(const ulonglong2*)(xr + ((jb2 ^ key) << 2));
        ull A[8] = {A0,A1,A2,A3,A4,A5,A6,A7};
        #pragma unroll
        for (int r = 0; r < 8; r++){
            fma2(acc[r][0], A[r], b0.x); fma2(acc[r][1], A[r], b0.y);
            fma2(acc[r][2], A[r], b1.x); fma2(acc[r][3], A[r], b1.y);
            fma2(acc[r][4], A[r], b2.x); fma2(acc[r][5], A[r], b2.y);
        }
    }
}

// -------------------- main fused point-branch kernel ------------------------
__global__ void __launch_bounds__(256, 1)
main_k(const float* __restrict__ pf, const float* __restrict__ scale,
       const float* __restrict__ center, const float* __restrict__ W3x,
       float* __restrict__ out)
{
    extern __shared__ float sm[];
    float* Xs = sm;               // 128 * 192 floats
    float* Zb = sm + NH*XROW;     // 2 * 16 * 192 floats (z chunks; later v partials)

    const int tid = threadIdx.x;
    const int tr  = tid & 15;     // row group: rows tr*8 .. tr*8+7
    const int tc  = tid >> 4;     // point group: points tc*4 .. tc*4+3
    const int b   = blockIdx.y;
    const int m0  = blockIdx.x * TSP;
    const float* pfb = pf + (size_t)b*NH*3*NM + m0;
    const int key_w = tr & 7;

    ull acc[8][6];

    // ---- GEMM1: q1 = W1x[:, :128] @ point_feat + bias -----------------------
    #pragma unroll
    for (int r = 0; r < 8; r++){
        const int o = tr*8 + r;
        #pragma unroll
        for (int d = 0; d < 3; d++){
            ull bb = bc2(g_bias1[(b*NH + o)*3 + d]);
            acc[r][2*d] = bb; acc[r][2*d+1] = bb;
        }
    }

    // stage chunk 0
    {
        float* dst = Zb;
        #pragma unroll
        for (int t = 0; t < 3; t++){
            int idx = tid + t*256;            // 0..767
            int row = idx >> 4;               // (k*3+d) 0..47
            int seg = idx & 15;
            cp16(dst + row*64 + seg*4, pfb + (size_t)row*NM + seg*4);
        }
        cpcommit();
    }

    const float* W0 = g_WT[0];
    int buf = 0;
    for (int kc0 = 0; kc0 < NH; kc0 += KC){
        cpwait0();
        __syncthreads();
        if (kc0 + KC < NH){
            float* dst = Zb + (buf^1)*(KC*XROW);
            #pragma unroll
            for (int t = 0; t < 3; t++){
                int idx = tid + t*256;
                int row = idx >> 4;
                int seg = idx & 15;
                cp16(dst + row*64 + seg*4, pfb + (size_t)((kc0+KC)*3 + row)*NM + seg*4);
            }
            cpcommit();
        }
        const float* zz = Zb + buf*(KC*XROW);
        #pragma unroll 4
        for (int kk = 0; kk < KC; kk++){
            const int k = kc0 + kk;
            const float4 a0 = __ldg((const float4*)(W0 + k*NH + tr*8));
            const float4 a1 = __ldg((const float4*)(W0 + k*NH + tr*8 + 4));
            ull A[8] = {bc2(a0.x),bc2(a0.y),bc2(a0.z),bc2(a0.w),
                        bc2(a1.x),bc2(a1.y),bc2(a1.z),bc2(a1.w)};
            const float* zr = zz + kk*XROW;
            #pragma unroll
            for (int d = 0; d < 3; d++){
                ulonglong2 bv = *(const ulonglong2*)(zr + d*64 + tc*4);
                #pragma unroll
                for (int r = 0; r < 8; r++){
                    fma2(acc[r][2*d],   A[r], bv.x);
                    fma2(acc[r][2*d+1], A[r], bv.y);
                }
            }
        }
        buf ^= 1;
    }

    // ---- epilogue 1a: scale by (1 + s2v/(|q|+eps)), store q1 to X -----------
    #pragma unroll
    for (int r = 0; r < 8; r++){
        const int o = tr*8 + r;
        const float sv = g_s2v1[b*NH + o];
        float q[3][4];
        #pragma unroll
        for (int d = 0; d < 3; d++){
            float2 u0 = u2f(acc[r][2*d]); float2 u1 = u2f(acc[r][2*d+1]);
            q[d][0]=u0.x; q[d][1]=u0.y; q[d][2]=u1.x; q[d][3]=u1.y;
        }
        #pragma unroll
        for (int p = 0; p < 4; p++){
            float n = sqrtf(q[0][p]*q[0][p] + q[1][p]*q[1][p] + q[2][p]*q[2][p]);
            float g = 1.0f + sv/(n + EPSN);
            q[0][p]*=g; q[1][p]*=g; q[2][p]*=g;
        }
        float* xo = Xs + o*XROW;
        #pragma unroll
        for (int d = 0; d < 3; d++){
            ulonglong2 v; v.x = f2u(q[d][0],q[d][1]); v.y = f2u(q[d][2],q[d][3]);
            *(ulonglong2*)(xo + (((d*16 + tc) ^ key_w) << 2)) = v;
        }
    }
    __syncthreads();

    // ---- GEMM d1 = W1x_d @ q1 ----------------------------------------------
    #pragma unroll
    for (int r = 0; r < 8; r++)
        #pragma unroll
        for (int c = 0; c < 6; c++) acc[r][c] = 0ull;
    gemm_x(g_WT[1], Xs, acc, tr, tc);
    __syncthreads();

    // ---- epilogue 1b: h1 = q1 - min(dot,0)*d_hat, overwrite X ---------------
    #pragma unroll
    for (int r = 0; r < 8; r++){
        const int o = tr*8 + r;
        float* xo = Xs + o*XROW;
        float q[3][4], dv[3][4];
        #pragma unroll
        for (int d = 0; d < 3; d++){
            ulonglong2 qv = *(const ulonglong2*)(xo + (((d*16 + tc) ^ key_w) << 2));
            float2 a = u2f(qv.x), c2 = u2f(qv.y);
            q[d][0]=a.x; q[d][1]=a.y; q[d][2]=c2.x; q[d][3]=c2.y;
            float2 u0 = u2f(acc[r][2*d]); float2 u1 = u2f(acc[r][2*d+1]);
            dv[d][0]=u0.x; dv[d][1]=u0.y; dv[d][2]=u1.x; dv[d][3]=u1.y;
        }
        #pragma unroll
        for (int p = 0; p < 4; p++){
            float nd = sqrtf(dv[0][p]*dv[0][p] + dv[1][p]*dv[1][p] + dv[2][p]*dv[2][p]) + EPSN;
            float inv = 1.0f / nd;
            float dot = (q[0][p]*dv[0][p] + q[1][p]*dv[1][p] + q[2][p]*dv[2][p]) * inv;
            float mf  = fminf(dot, 0.0f) * inv;
            q[0][p] -= mf*dv[0][p]; q[1][p] -= mf*dv[1][p]; q[2][p] -= mf*dv[2][p];
        }
        #pragma unroll
        for (int d = 0; d < 3; d++){
            ulonglong2 v; v.x = f2u(q[d][0],q[d][1]); v.y = f2u(q[d][2],q[d][3]);
            *(ulonglong2*)(xo + (((d*16 + tc) ^ key_w) << 2)) = v;
        }
    }
    __syncthreads();

    // ---- GEMM q2 = W2x @ h1 -------------------------------------------------
    #pragma unroll
    for (int r = 0; r < 8; r++)
        #pragma unroll
        for (int c = 0; c < 6; c++) acc[r][c] = 0ull;
    gemm_x(g_WT[2], Xs, acc, tr, tc);
    __syncthreads();

    // store q2 (no scale)
    #pragma unroll
    for (int r = 0; r < 8; r++){
        const int o = tr*8 + r;
        float* xo = Xs + o*XROW;
        #pragma unroll
        for (int d = 0; d < 3; d++){
            ulonglong2 v; v.x = acc[r][2*d]; v.y = acc[r][2*d+1];
            *(ulonglong2*)(xo + (((d*16 + tc) ^ key_w) << 2)) = v;
        }
    }
    __syncthreads();

    // ---- GEMM d2 = W2x_d @ q2 ----------------------------------------------
    #pragma unroll
    for (int r = 0; r < 8; r++)
        #pragma unroll
        for (int c = 0; c < 6; c++) acc[r][c] = 0ull;
    gemm_x(g_WT[3], Xs, acc, tr, tc);
    __syncthreads();

    // ---- epilogue 2 + W3x partials (h2 kept in registers) -------------------
    float w30[8], w31[8];
    #pragma unroll
    for (int r = 0; r < 8; r++){
        w30[r] = __ldg(W3x + tr*8 + r);
        w31[r] = __ldg(W3x + NH + tr*8 + r);
    }
    float vp[2][3][4];
    #pragma unroll
    for (int o2 = 0; o2 < 2; o2++)
        #pragma unroll
        for (int d = 0; d < 3; d++)
            #pragma unroll
            for (int p = 0; p < 4; p++) vp[o2][d][p] = 0.0f;

    #pragma unroll
    for (int r = 0; r < 8; r++){
        const int o = tr*8 + r;
        const float* xo = Xs + o*XROW;
        float q[3][4], dv[3][4];
        #pragma unroll
        for (int d = 0; d < 3; d++){
            ulonglong2 qv = *(const ulonglong2*)(xo + (((d*16 + tc) ^ key_w) << 2));
            float2 a = u2f(qv.x), c2 = u2f(qv.y);
            q[d][0]=a.x; q[d][1]=a.y; q[d][2]=c2.x; q[d][3]=c2.y;
            float2 u0 = u2f(acc[r][2*d]); float2 u1 = u2f(acc[r][2*d+1]);
            dv[d][0]=u0.x; dv[d][1]=u0.y; dv[d][2]=u1.x; dv[d][3]=u1.y;
        }
        #pragma unroll
        for (int p = 0; p < 4; p++){
            float nd = sqrtf(dv[0][p]*dv[0][p] + dv[1][p]*dv[1][p] + dv[2][p]*dv[2][p]) + EPSN;
            float inv = 1.0f / nd;
            float dot = (q[0][p]*dv[0][p] + q[1][p]*dv[1][p] + q[2][p]*dv[2][p]) * inv;
            float mf  = fminf(dot, 0.0f) * inv;
            float h0 = q[0][p] - mf*dv[0][p];
            float h1 = q[1][p] - mf*dv[1][p];
            float h2 = q[2][p] - mf*dv[2][p];
            vp[0][0][p] += w30[r]*h0; vp[0][1][p] += w30[r]*h1; vp[0][2][p] += w30[r]*h2;
            vp[1][0][p] += w31[r]*h0; vp[1][1][p] += w31[r]*h1; vp[1][2][p] += w31[r]*h2;
        }
    }

    // partial reduction buffer in Zb: [tr][o2][d][64]
    float* zv = Zb;
    #pragma unroll
    for (int o2 = 0; o2 < 2; o2++)
        #pragma unroll
        for (int d = 0; d < 3; d++)
            *(float4*)(zv + ((tr*2 + o2)*3 + d)*64 + tc*4) =
                make_float4(vp[o2][d][0], vp[o2][d][1], vp[o2][d][2], vp[o2][d][3]);
    __syncthreads();

    // reduce 16 partials, transform, store offsets
    const float sc = scale[b];
    for (int u = tid; u < 384; u += 256){
        const int p  = u & 63;
        const int dd = (u >> 6) % 3;
        const int o2 = u / 192;
        float s = 0.0f;
        #pragma unroll
        for (int t = 0; t < 16; t++) s += zv[((t*2 + o2)*3 + dd)*64 + p];
        if (o2 == 0) s = s*sc + center[b*3 + dd];
        out[((size_t)b*NM + m0 + p)*6 + o2*3 + dd] = s;
    }
}

// -------------------- prep: z_state, bias, s2v, gripper branch ---------------
__global__ void prep_k(const float* __restrict__ z_pos, const float* __restrict__ z_dir,
                       const float* __restrict__ z_scalar, const float* __restrict__ gfeat,
                       const float* __restrict__ center, const float* __restrict__ scale,
                       const float* __restrict__ W1x, const float* __restrict__ W1x_s,
                       const float* __restrict__ W1g, const float* __restrict__ W1g_d,
                       const float* __restrict__ W1g_s, const float* __restrict__ W2g,
                       const float* __restrict__ W2g_d, const float* __restrict__ Wg_vs,
                       float* __restrict__ out)
{
    __shared__ float vg[136*3];
    __shared__ float bq[128*3];
    __shared__ float bh[128*3];
    __shared__ float nh[128];
    __shared__ float zs[8*3];
    const int b = blockIdx.x;
    const int o = threadIdx.x;   // 128 threads

    if (o < 24){
        int r = o/3, d = o%3;
        float v = (r < 2) ? (z_pos[(b*2 + r)*3 + d] - center[b*3 + d]) / scale[b]
                          : z_dir[(b*6 + (r-2))*3 + d];
        zs[r*3 + d] = v;
        g_zstate[(b*8 + r)*3 + d] = v;
        if (r < 2) g_zposn[(b*2 + r)*3 + d] = v;
    }
    __syncthreads();

    // point-branch constants
    {
        float s2 = W1x_s[o*2+0]*z_scalar[b*2+0] + W1x_s[o*2+1]*z_scalar[b*2+1];
        g_s2v1[b*NH + o] = s2;
        #pragma unroll
        for (int d = 0; d < 3; d++){
            float s = 0.0f;
            #pragma unroll
            for (int k = 0; k < 8; k++) s += W1x[o*136 + 128 + k] * zs[k*3 + d];
            g_bias1[(b*NH + o)*3 + d] = s;
        }
    }

    // build vg = [global_feat ; z_state]
    for (int i = o; i < 408; i += 128){
        int c = i/3, d = i%3;
        vg[i] = (c < 128) ? gfeat[(b*128 + c)*3 + d] : zs[(c-128)*3 + d];
    }
    __syncthreads();

    // layer 1 (with scalar gate)
    float q[3];
    #pragma unroll
    for (int d = 0; d < 3; d++){
        float s = 0.0f;
        for (int c = 0; c < 136; c++) s += W1g[o*136 + c] * vg[c*3 + d];
        q[d] = s;
    }
    {
        float sg = W1g_s[o*2+0]*z_scalar[b*2+0] + W1g_s[o*2+1]*z_scalar[b*2+1];
        float n = sqrtf(q[0]*q[0] + q[1]*q[1] + q[2]*q[2]);
        float g = 1.0f + sg/(n + EPSN);
        q[0]*=g; q[1]*=g; q[2]*=g;
    }
    bq[o*3+0]=q[0]; bq[o*3+1]=q[1]; bq[o*3+2]=q[2];
    __syncthreads();
    float dv[3];
    #pragma unroll
    for (int d = 0; d < 3; d++){
        float s = 0.0f;
        for (int c = 0; c < 128; c++) s += W1g_d[o*128 + c] * bq[c*3 + d];
        dv[d] = s;
    }
    {
        float nd = sqrtf(dv[0]*dv[0]+dv[1]*dv[1]+dv[2]*dv[2]) + EPSN;
        float inv = 1.0f/nd;
        float dot = (q[0]*dv[0]+q[1]*dv[1]+q[2]*dv[2])*inv;
        float mf = fminf(dot, 0.0f)*inv;
        q[0]-=mf*dv[0]; q[1]-=mf*dv[1]; q[2]-=mf*dv[2];
    }
    bh[o*3+0]=q[0]; bh[o*3+1]=q[1]; bh[o*3+2]=q[2];
    __syncthreads();

    // layer 2 (no gate)
    #pragma unroll
    for (int d = 0; d < 3; d++){
        float s = 0.0f;
        for (int c = 0; c < 128; c++) s += W2g[o*128 + c] * bh[c*3 + d];
        q[d] = s;
    }
    bq[o*3+0]=q[0]; bq[o*3+1]=q[1]; bq[o*3+2]=q[2];
    __syncthreads();
    #pragma unroll
    for (int d = 0; d < 3; d++){
        float s = 0.0f;
        for (int c = 0; c < 128; c++) s += W2g_d[o*128 + c] * bq[c*3 + d];
        dv[d] = s;
    }
    {
        float nd = sqrtf(dv[0]*dv[0]+dv[1]*dv[1]+dv[2]*dv[2]) + EPSN;
        float inv = 1.0f/nd;
        float dot = (q[0]*dv[0]+q[1]*dv[1]+q[2]*dv[2])*inv;
        float mf = fminf(dot, 0.0f)*inv;
        q[0]-=mf*dv[0]; q[1]-=mf*dv[1]; q[2]-=mf*dv[2];
    }
    nh[o] = sqrtf(q[0]*q[0]+q[1]*q[1]+q[2]*q[2]);
    __syncthreads();

    if (o < 2){
        float s = 0.0f;
        for (int c = 0; c < 128; c++) s += Wg_vs[o*128 + c] * nh[c];
        float gr = 1.0f/(1.0f + expf(-s));
        g_grip[b*2 + o] = gr;
        out[GRIP_OFF + b*2 + o] = gr;
    }
}

// -------------------- weight transpose --------------------------------------
__global__ void transpose_k(const float* __restrict__ W1x, const float* __restrict__ W1x_d,
                            const float* __restrict__ W2x, const float* __restrict__ W2x_d)
{
    const int m = blockIdx.x;
    const float* src = (m==0) ? W1x : (m==1) ? W1x_d : (m==2) ? W2x : W2x_d;
    const int rl = (m==0) ? 136 : 128;
    for (int i = threadIdx.x; i < NH*NH; i += blockDim.x){
        int c = i >> 7, o = i & 127;
        g_WT[m][c*NH + o] = src[o*rl + c];
    }
}

// -------------------- argmin over points -------------------------------------
__global__ void argmin_k(const float* __restrict__ pc)
{
    __shared__ float sv[256];
    __shared__ int   si[256];
    const int be = blockIdx.x;     // b*2+e
    const int b = be >> 1;
    const float zx = g_zposn[be*3+0], zy = g_zposn[be*3+1], zz = g_zposn[be*3+2];
    const float* p = pc + (size_t)b*NM*3;
    float best = 3.4e38f; int bi = 0;
    for (int m = threadIdx.x; m < NM; m += blockDim.x){
        float dx = zx - p[m*3+0], dy = zy - p[m*3+1], dz = zz - p[m*3+2];
        float d = sqrtf(dx*dx + dy*dy + dz*dz);
        if (d < best){ best = d; bi = m; }
    }
    sv[threadIdx.x] = best; si[threadIdx.x] = bi;
    __syncthreads();
    for (int s = 128; s > 0; s >>= 1){
        if (threadIdx.x < s){
            float ov = sv[threadIdx.x + s]; int oi = si[threadIdx.x + s];
            if (ov < sv[threadIdx.x] || (ov == sv[threadIdx.x] && oi < si[threadIdx.x])){
                sv[threadIdx.x] = ov; si[threadIdx.x] = oi;
            }
        }
        __syncthreads();
    }
    if (threadIdx.x == 0) g_closest[be] = si[0];
}

// -------------------- final ac assembly --------------------------------------
__global__ void assemble_k(float* __restrict__ out)
{
    const int t = threadIdx.x;
    if (t < 112){
        int b = t/14, j = t%14, e = j/7, r = j%7;
        float v;
        if (r == 0) v = g_grip[b*2 + e];
        else {
            int m = g_closest[b*2 + e];
            v = out[((size_t)b*NM + m)*6 + (r-1)];
        }
        out[AC_OFF + t] = v;
    }
}

// -------------------- launch -------------------------------------------------
extern "C" void kernel_launch(void* const* d_in, const int* in_sizes, int n_in,
                              void* d_out, int out_size)
{
    const float* pc        = (const float*)d_in[0];
    const float* z_pos     = (const float*)d_in[1];
    const float* z_dir     = (const float*)d_in[2];
    const float* z_scalar  = (const float*)d_in[3];
    const float* point_feat= (const float*)d_in[4];
    const float* gfeat     = (const float*)d_in[5];
    const float* center    = (const float*)d_in[6];
    const float* scale     = (const float*)d_in[7];
    const float* W1x       = (const float*)d_in[8];
    const float* W1x_d     = (const float*)d_in[9];
    const float* W1x_s     = (const float*)d_in[10];
    const float* W2x       = (const float*)d_in[11];
    const float* W2x_d     = (const float*)d_in[12];
    const float* W3x       = (const float*)d_in[13];
    const float* W1g       = (const float*)d_in[14];
    const float* W1g_d     = (const float*)d_in[15];
    const float* W1g_s     = (const float*)d_in[16];
    const float* W2g       = (const float*)d_in[17];
    const float* W2g_d     = (const float*)d_in[18];
    const float* Wg_vs     = (const float*)d_in[19];
    float* out = (float*)d_out;

    const size_t smem = (size_t)(NH*XROW + 2*KC*XROW) * sizeof(float);  // 122880 B
    cudaFuncSetAttribute(main_k, cudaFuncAttributeMaxDynamicSharedMemorySize, (int)smem);

    transpose_k<<<4, 256>>>(W1x, W1x_d, W2x, W2x_d);
    prep_k<<<NB, 128>>>(z_pos, z_dir, z_scalar, gfeat, center, scale,
                        W1x, W1x_s, W1g, W1g_d, W1g_s, W2g, W2g_d, Wg_vs, out);
    argmin_k<<<16, 256>>>(pc);
    main_k<<<dim3(NM/TSP, NB), 256, smem>>>(point_feat, scale, center, W3x, out);
    assemble_k<<<1, 128>>>(out);
}

// round 8
// speedup vs baseline: 1.1905x; 1.1905x over previous
#include <cuda_runtime.h>
#include <cuda_bf16.h>
#include <cstdint>
#include <math.h>

#define EPSN 1e-6f
#define NB 8
#define NM 16384
#define GRIP_OFF (NB*NM*6)
#define AC_OFF   (GRIP_OFF+16)
#define ROWB 512                 // bytes per smem image row (256 bf16 slots, 192 used)
#define IMG  65536               // bytes per image (128 rows)

__device__ __align__(16) __nv_bfloat16 g_Whi[5][16384];   // [o][k] row-major 128x128
__device__ __align__(16) __nv_bfloat16 g_Wlo[5][16384];
__device__ float g_bias1[NB*128*3];
__device__ float g_s2v1[NB*128];
__device__ float g_zposn[NB*2*3];
__device__ float g_grip[NB*2];
__device__ int   g_closest[NB*2];

// ---------------- helpers ----------------
__device__ __forceinline__ uint32_t smem_u32(const void* p){
    uint32_t a; asm("{ .reg .u64 t; cvta.to.shared.u64 t, %1; cvt.u32.u64 %0, t; }" : "=r"(a) : "l"(p)); return a;
}
__device__ __forceinline__ uint32_t pk_bf(float a, float b){
    return (uint32_t)__bfloat16_as_ushort(__float2bfloat16(a)) |
           ((uint32_t)__bfloat16_as_ushort(__float2bfloat16(b)) << 16);
}
__device__ __forceinline__ float bl(uint32_t v){ return __bfloat162float(__ushort_as_bfloat16((unsigned short)(v & 0xFFFF))); }
__device__ __forceinline__ float bhf(uint32_t v){ return __bfloat162float(__ushort_as_bfloat16((unsigned short)(v >> 16))); }

__device__ __forceinline__ void mma_bf16(float* c, const uint32_t* a, uint32_t b0, uint32_t b1){
    asm("mma.sync.aligned.m16n8k16.row.col.f32.bf16.bf16.f32 "
        "{%0,%1,%2,%3},{%4,%5,%6,%7},{%8,%9},{%0,%1,%2,%3};"
        : "+f"(c[0]), "+f"(c[1]), "+f"(c[2]), "+f"(c[3])
        : "r"(a[0]), "r"(a[1]), "r"(a[2]), "r"(a[3]), "r"(b0), "r"(b1));
}
__device__ __forceinline__ void ldsm4t(uint32_t& r0, uint32_t& r1, uint32_t& r2, uint32_t& r3, uint32_t addr){
    asm volatile("ldmatrix.sync.aligned.m8n8.x4.trans.shared.b16 {%0,%1,%2,%3}, [%4];"
        : "=r"(r0), "=r"(r1), "=r"(r2), "=r"(r3) : "r"(addr) : "memory");
}

// one GEMM layer: D[16 rows/warp x NTN*8 cols] = 3 compensation passes
template<int NTN>
__device__ __forceinline__ void layer_mma(float acc[][4],
    const __nv_bfloat16* Whi, const __nv_bfloat16* Wlo,
    uint32_t sbH, uint32_t sbL, int NT0, int mrow0,
    int qr, int cb, int rB, int chL, int key)
{
    #pragma unroll
    for (int i = 0; i < NTN; i++){ acc[i][0]=0.f; acc[i][1]=0.f; acc[i][2]=0.f; acc[i][3]=0.f; }

    uint32_t af[8][4];
    {
        const __nv_bfloat16* pw = Whi + (mrow0 + qr)*128 + cb;
        #pragma unroll
        for (int kt = 0; kt < 8; kt++){
            af[kt][0] = *(const uint32_t*)(pw + kt*16);
            af[kt][1] = *(const uint32_t*)(pw + kt*16 + 1024);
            af[kt][2] = *(const uint32_t*)(pw + kt*16 + 8);
            af[kt][3] = *(const uint32_t*)(pw + kt*16 + 1032);
        }
    }
    #pragma unroll 1
    for (int pass = 0; pass < 3; pass++){
        if (pass == 2){
            const __nv_bfloat16* pw = Wlo + (mrow0 + qr)*128 + cb;
            #pragma unroll
            for (int kt = 0; kt < 8; kt++){
                af[kt][0] = *(const uint32_t*)(pw + kt*16);
                af[kt][1] = *(const uint32_t*)(pw + kt*16 + 1024);
                af[kt][2] = *(const uint32_t*)(pw + kt*16 + 8);
                af[kt][3] = *(const uint32_t*)(pw + kt*16 + 1032);
            }
        }
        const uint32_t rowbase = ((pass == 1) ? sbL : sbH) + rB*ROWB;
        #pragma unroll
        for (int kt = 0; kt < 8; kt++){
            const uint32_t kb = rowbase + kt*16*ROWB;
            #pragma unroll
            for (int t = 0; t < NTN/2; t++){
                uint32_t addr = kb + ((uint32_t)((NT0 + 2*t + chL) ^ key) << 4);
                uint32_t b0, b1, b2, b3;
                ldsm4t(b0, b1, b2, b3, addr);
                mma_bf16(acc[2*t],   af[kt], b0, b1);
                mma_bf16(acc[2*t+1], af[kt], b2, b3);
            }
        }
    }
}

// epilogues: MODE 0 = bias+gate, 1 = LNA, 2 = raw copy. Writes split h back to images.
template<int MODE>
__device__ __forceinline__ void epi(float acc[][4], char* sm, int o0, int cb, int bbase)
{
    #pragma unroll
    for (int r = 0; r < 2; r++){
        const int o = o0 + r*8;
        const int keyo = o & 7;
        float b0=0.f, b1=0.f, b2=0.f, sv=0.f;
        if (MODE == 0){
            b0 = g_bias1[(bbase+o)*3+0]; b1 = g_bias1[(bbase+o)*3+1]; b2 = g_bias1[(bbase+o)*3+2];
            sv = g_s2v1[bbase+o];
        }
        #pragma unroll
        for (int pt = 0; pt < 8; pt++){
            uint32_t offd[3];
            #pragma unroll
            for (int d = 0; d < 3; d++)
                offd[d] = (uint32_t)(o*ROWB + (((d*8+pt) ^ keyo) << 4) + cb*2);
            float x0 = acc[pt][2*r],    x1 = acc[pt][2*r+1];
            float y0 = acc[8+pt][2*r],  y1 = acc[8+pt][2*r+1];
            float z0 = acc[16+pt][2*r], z1 = acc[16+pt][2*r+1];
            float h[3][2];
            if (MODE == 0){
                float q00=x0+b0, q10=y0+b1, q20=z0+b2;
                float q01=x1+b0, q11=y1+b1, q21=z1+b2;
                float g0 = 1.0f + sv/(sqrtf(q00*q00+q10*q10+q20*q20)+EPSN);
                float g1 = 1.0f + sv/(sqrtf(q01*q01+q11*q11+q21*q21)+EPSN);
                h[0][0]=q00*g0; h[1][0]=q10*g0; h[2][0]=q20*g0;
                h[0][1]=q01*g1; h[1][1]=q11*g1; h[2][1]=q21*g1;
            } else if (MODE == 2){
                h[0][0]=x0; h[0][1]=x1; h[1][0]=y0; h[1][1]=y1; h[2][0]=z0; h[2][1]=z1;
            } else {
                float q[3][2];
                #pragma unroll
                for (int d = 0; d < 3; d++){
                    uint32_t qh = *(uint32_t*)(sm + offd[d]);
                    uint32_t ql = *(uint32_t*)(sm + IMG + offd[d]);
                    q[d][0] = bl(qh)+bl(ql); q[d][1] = bhf(qh)+bhf(ql);
                }
                float inv0 = 1.0f/(sqrtf(x0*x0+y0*y0+z0*z0)+EPSN);
                float mf0  = fminf((q[0][0]*x0+q[1][0]*y0+q[2][0]*z0)*inv0, 0.0f)*inv0;
                float inv1 = 1.0f/(sqrtf(x1*x1+y1*y1+z1*z1)+EPSN);
                float mf1  = fminf((q[0][1]*x1+q[1][1]*y1+q[2][1]*z1)*inv1, 0.0f)*inv1;
                h[0][0]=q[0][0]-mf0*x0; h[1][0]=q[1][0]-mf0*y0; h[2][0]=q[2][0]-mf0*z0;
                h[0][1]=q[0][1]-mf1*x1; h[1][1]=q[1][1]-mf1*y1; h[2][1]=q[2][1]-mf1*z1;
            }
            #pragma unroll
            for (int d = 0; d < 3; d++){
                uint32_t hw = pk_bf(h[d][0], h[d][1]);
                uint32_t lw = pk_bf(h[d][0]-bl(hw), h[d][1]-bhf(hw));
                *(uint32_t*)(sm + offd[d])       = hw;
                *(uint32_t*)(sm + IMG + offd[d]) = lw;
            }
        }
    }
}

// ---------------- main kernel ----------------
__global__ void __launch_bounds__(256, 1)
main_mma(const float* __restrict__ pf, const float* __restrict__ scale,
         const float* __restrict__ center, float* __restrict__ out)
{
    extern __shared__ char sm[];
    const uint32_t sbH = smem_u32(sm), sbL = sbH + IMG;
    const int tid = threadIdx.x, w = tid >> 5, lane = tid & 31;
    const int b = blockIdx.y, m0 = blockIdx.x * 64;
    const int qr = lane >> 2, cb = (lane & 3)*2;
    const int rB = lane & 15, chL = lane >> 4, key = rB & 7;

    // build hi/lo activation images from point_feat: row = channel c, col n = d*64+p
    #pragma unroll 1
    for (int it = 0; it < 24; it++){
        int idx = tid + it*256;
        int seg = idx & 15, d = (idx >> 4) % 3, c = idx / 48;
        float4 v = __ldg((const float4*)(pf + (((size_t)(b*128+c)*3+d)*NM + m0 + seg*4)));
        int n0 = d*64 + seg*4;
        uint32_t off = (uint32_t)(c*ROWB + (((n0>>3) ^ (c&7)) << 4) + (n0&7)*2);
        uint32_t h01 = pk_bf(v.x, v.y), h23 = pk_bf(v.z, v.w);
        uint32_t l01 = pk_bf(v.x - bl(h01), v.y - bhf(h01));
        uint32_t l23 = pk_bf(v.z - bl(h23), v.w - bhf(h23));
        *(uint32_t*)(sm + off)           = h01;
        *(uint32_t*)(sm + off + 4)       = h23;
        *(uint32_t*)(sm + IMG + off)     = l01;
        *(uint32_t*)(sm + IMG + off + 4) = l23;
    }
    __syncthreads();

    float acc[24][4];
    const int o0 = w*16 + qr;
    const int bbase = b*128;

    layer_mma<24>(acc, g_Whi[0], g_Wlo[0], sbH, sbL, 0, w*16, qr, cb, rB, chL, key);
    __syncthreads();
    epi<0>(acc, sm, o0, cb, bbase);
    __syncthreads();

    layer_mma<24>(acc, g_Whi[1], g_Wlo[1], sbH, sbL, 0, w*16, qr, cb, rB, chL, key);
    __syncthreads();
    epi<1>(acc, sm, o0, cb, bbase);
    __syncthreads();

    layer_mma<24>(acc, g_Whi[2], g_Wlo[2], sbH, sbL, 0, w*16, qr, cb, rB, chL, key);
    __syncthreads();
    epi<2>(acc, sm, o0, cb, bbase);
    __syncthreads();

    layer_mma<24>(acc, g_Whi[3], g_Wlo[3], sbH, sbL, 0, w*16, qr, cb, rB, chL, key);
    __syncthreads();
    epi<1>(acc, sm, o0, cb, bbase);
    __syncthreads();

    // final projection: M=16 (rows 0-1 valid), warps 0-5 cover 4 n-tiles each
    if (w < 6){
        layer_mma<4>(acc, g_Whi[4], g_Wlo[4], sbH, sbL, 4*w, 0, qr, cb, rB, chL, key);
        if (lane < 8){
            const float sc = __ldg(scale + b);
            const int o2 = qr;   // 0 or 1
            #pragma unroll
            for (int t = 0; t < 4; t++){
                int n0 = (4*w + t)*8 + cb;
                #pragma unroll
                for (int j = 0; j < 2; j++){
                    int n = n0 + j, d = n >> 6, p = n & 63;
                    float v = acc[t][j];
                    if (o2 == 0) v = v*sc + __ldg(center + b*3 + d);
                    out[((size_t)b*NM + m0 + p)*6 + o2*3 + d] = v;
                }
            }
        }
    }
}

// ---------------- weight split images ----------------
__global__ void buildW_k(const float* __restrict__ W1x, const float* __restrict__ W1xd,
                         const float* __restrict__ W2x, const float* __restrict__ W2xd,
                         const float* __restrict__ W3x)
{
    const int m = blockIdx.x;
    for (int i = threadIdx.x; i < 16384; i += 256){
        int o = i >> 7, k = i & 127;
        float w = (m==0) ? W1x[o*136+k] : (m==1) ? W1xd[o*128+k] : (m==2) ? W2x[o*128+k]
                : (m==3) ? W2xd[o*128+k] : ((o<2) ? W3x[o*128+k] : 0.0f);
        __nv_bfloat16 h = __float2bfloat16(w);
        g_Whi[m][i] = h;
        g_Wlo[m][i] = __float2bfloat16(w - __bfloat162float(h));
    }
}

// ---------------- prep: bias/s2v + gripper branch (fp32) ----------------
__global__ void prep_k(const float* __restrict__ z_pos, const float* __restrict__ z_dir,
                       const float* __restrict__ z_scalar, const float* __restrict__ gfeat,
                       const float* __restrict__ center, const float* __restrict__ scale,
                       const float* __restrict__ W1x, const float* __restrict__ W1x_s,
                       const float* __restrict__ W1g, const float* __restrict__ W1g_d,
                       const float* __restrict__ W1g_s, const float* __restrict__ W2g,
                       const float* __restrict__ W2g_d, const float* __restrict__ Wg_vs,
                       float* __restrict__ out)
{
    __shared__ float vg[136*3], bq[128*3], bhm[128*3], nh[128], zs[8*3];
    const int b = blockIdx.x, o = threadIdx.x;
    if (o < 24){
        int r = o/3, d = o%3;
        float v = (r < 2) ? (z_pos[(b*2+r)*3+d] - center[b*3+d]) / scale[b] : z_dir[(b*6+(r-2))*3+d];
        zs[r*3+d] = v;
        if (r < 2) g_zposn[(b*2+r)*3+d] = v;
    }
    __syncthreads();
    {
        g_s2v1[b*128+o] = W1x_s[o*2]*z_scalar[b*2] + W1x_s[o*2+1]*z_scalar[b*2+1];
        #pragma unroll
        for (int d = 0; d < 3; d++){
            float s = 0.0f;
            #pragma unroll
            for (int k = 0; k < 8; k++) s += W1x[o*136 + 128 + k] * zs[k*3+d];
            g_bias1[(b*128+o)*3+d] = s;
        }
    }
    for (int i = o; i < 408; i += 128){
        int c = i/3, d = i%3;
        vg[i] = (c < 128) ? gfeat[(b*128+c)*3+d] : zs[(c-128)*3+d];
    }
    __syncthreads();
    float q[3], dv[3];
    #pragma unroll
    for (int d = 0; d < 3; d++){ float s=0; for (int c=0;c<136;c++) s += W1g[o*136+c]*vg[c*3+d]; q[d]=s; }
    {
        float sg = W1g_s[o*2]*z_scalar[b*2] + W1g_s[o*2+1]*z_scalar[b*2+1];
        float g = 1.0f + sg/(sqrtf(q[0]*q[0]+q[1]*q[1]+q[2]*q[2])+EPSN);
        q[0]*=g; q[1]*=g; q[2]*=g;
    }
    bq[o*3]=q[0]; bq[o*3+1]=q[1]; bq[o*3+2]=q[2];
    __syncthreads();
    #pragma unroll
    for (int d = 0; d < 3; d++){ float s=0; for (int c=0;c<128;c++) s += W1g_d[o*128+c]*bq[c*3+d]; dv[d]=s; }
    {
        float inv = 1.0f/(sqrtf(dv[0]*dv[0]+dv[1]*dv[1]+dv[2]*dv[2]) + EPSN);
        float mf = fminf((q[0]*dv[0]+q[1]*dv[1]+q[2]*dv[2])*inv, 0.0f)*inv;
        q[0]-=mf*dv[0]; q[1]-=mf*dv[1]; q[2]-=mf*dv[2];
    }
    bhm[o*3]=q[0]; bhm[o*3+1]=q[1]; bhm[o*3+2]=q[2];
    __syncthreads();
    #pragma unroll
    for (int d = 0; d < 3; d++){ float s=0; for (int c=0;c<128;c++) s += W2g[o*128+c]*bhm[c*3+d]; q[d]=s; }
    bq[o*3]=q[0]; bq[o*3+1]=q[1]; bq[o*3+2]=q[2];
    __syncthreads();
    #pragma unroll
    for (int d = 0; d < 3; d++){ float s=0; for (int c=0;c<128;c++) s += W2g_d[o*128+c]*bq[c*3+d]; dv[d]=s; }
    {
        float inv = 1.0f/(sqrtf(dv[0]*dv[0]+dv[1]*dv[1]+dv[2]*dv[2]) + EPSN);
        float mf = fminf((q[0]*dv[0]+q[1]*dv[1]+q[2]*dv[2])*inv, 0.0f)*inv;
        q[0]-=mf*dv[0]; q[1]-=mf*dv[1]; q[2]-=mf*dv[2];
    }
    nh[o] = sqrtf(q[0]*q[0]+q[1]*q[1]+q[2]*q[2]);
    __syncthreads();
    if (o < 2){
        float s = 0; for (int c = 0; c < 128; c++) s += Wg_vs[o*128+c]*nh[c];
        float gr = 1.0f/(1.0f+expf(-s));
        g_grip[b*2+o] = gr;
        out[GRIP_OFF + b*2+o] = gr;
    }
}

__global__ void argmin_k(const float* __restrict__ pc)
{
    __shared__ float sv[256]; __shared__ int si[256];
    const int be = blockIdx.x, b = be >> 1;
    const float zx = g_zposn[be*3], zy = g_zposn[be*3+1], zz = g_zposn[be*3+2];
    const float* p = pc + (size_t)b*NM*3;
    float best = 3.4e38f; int bi = 0;
    for (int m = threadIdx.x; m < NM; m += blockDim.x){
        float dx=zx-p[m*3], dy=zy-p[m*3+1], dz=zz-p[m*3+2];
        float d = sqrtf(dx*dx+dy*dy+dz*dz);
        if (d < best){ best = d; bi = m; }
    }
    sv[threadIdx.x]=best; si[threadIdx.x]=bi;
    __syncthreads();
    for (int s = 128; s > 0; s >>= 1){
        if (threadIdx.x < s){
            float ov = sv[threadIdx.x+s]; int oi = si[threadIdx.x+s];
            if (ov < sv[threadIdx.x] || (ov == sv[threadIdx.x] && oi < si[threadIdx.x])){
                sv[threadIdx.x]=ov; si[threadIdx.x]=oi;
            }
        }
        __syncthreads();
    }
    if (threadIdx.x == 0) g_closest[be] = si[0];
}

__global__ void assemble_k(float* __restrict__ out)
{
    const int t = threadIdx.x;
    if (t < 112){
        int b = t/14, j = t%14, e = j/7, r = j%7;
        float v;
        if (r == 0) v = g_grip[b*2+e];
        else { int m = g_closest[b*2+e]; v = out[((size_t)b*NM+m)*6 + (r-1)]; }
        out[AC_OFF + t] = v;
    }
}

// ---------------- launch ----------------
extern "C" void kernel_launch(void* const* d_in, const int* in_sizes, int n_in,
                              void* d_out, int out_size)
{
    const float* pc        = (const float*)d_in[0];
    const float* z_pos     = (const float*)d_in[1];
    const float* z_dir     = (const float*)d_in[2];
    const float* z_scalar  = (const float*)d_in[3];
    const float* point_feat= (const float*)d_in[4];
    const float* gfeat     = (const float*)d_in[5];
    const float* center    = (const float*)d_in[6];
    const float* scale     = (const float*)d_in[7];
    const float* W1x       = (const float*)d_in[8];
    const float* W1x_d     = (const float*)d_in[9];
    const float* W1x_s     = (const float*)d_in[10];
    const float* W2x       = (const float*)d_in[11];
    const float* W2x_d     = (const float*)d_in[12];
    const float* W3x       = (const float*)d_in[13];
    const float* W1g       = (const float*)d_in[14];
    const float* W1g_d     = (const float*)d_in[15];
    const float* W1g_s     = (const float*)d_in[16];
    const float* W2g       = (const float*)d_in[17];
    const float* W2g_d     = (const float*)d_in[18];
    const float* Wg_vs     = (const float*)d_in[19];
    float* out = (float*)d_out;

    cudaFuncSetAttribute(main_mma, cudaFuncAttributeMaxDynamicSharedMemorySize, 2*IMG);

    buildW_k<<<5, 256>>>(W1x, W1x_d, W2x, W2x_d, W3x);
    prep_k<<<NB, 128>>>(z_pos, z_dir, z_scalar, gfeat, center, scale,
                        W1x, W1x_s, W1g, W1g_d, W1g_s, W2g, W2g_d, Wg_vs, out);
    argmin_k<<<16, 256>>>(pc);
    main_mma<<<dim3(NM/64, NB), 256, 2*IMG>>>(point_feat, scale, center, out);
    assemble_k<<<1, 128>>>(out);
}

// round 11
// speedup vs baseline: 1.3139x; 1.1037x over previous
#include <cuda_runtime.h>
#include <cuda_bf16.h>
#include <cstdint>
#include <math.h>

#define EPSN 1e-6f
#define NB 8
#define NM 16384
#define GRIP_OFF (NB*NM*6)
#define AC_OFF   (GRIP_OFF+16)
#define ROWB 384                 // bytes per smem image row (192 bf16 slots)
#define IMG  49152               // bytes per image (128 rows)

__device__ __align__(16) __nv_bfloat16 g_Whi[5][16384];   // [o][k] row-major 128x128
__device__ __align__(16) __nv_bfloat16 g_Wlo[5][16384];
__device__ float g_bias1[NB*128*3];
__device__ float g_s2v1[NB*128];
__device__ float g_zposn[NB*2*3];
__device__ float g_grip[NB*2];
__device__ int   g_closest[NB*2];

// ---------------- helpers ----------------
__device__ __forceinline__ uint32_t smem_u32(const void* p){
    uint32_t a; asm("{ .reg .u64 t; cvta.to.shared.u64 t, %1; cvt.u32.u64 %0, t; }" : "=r"(a) : "l"(p)); return a;
}
__device__ __forceinline__ uint32_t pk_bf(float a, float b){
    return (uint32_t)__bfloat16_as_ushort(__float2bfloat16(a)) |
           ((uint32_t)__bfloat16_as_ushort(__float2bfloat16(b)) << 16);
}
__device__ __forceinline__ float bl(uint32_t v){ return __bfloat162float(__ushort_as_bfloat16((unsigned short)(v & 0xFFFF))); }
__device__ __forceinline__ float bhf(uint32_t v){ return __bfloat162float(__ushort_as_bfloat16((unsigned short)(v >> 16))); }

__device__ __forceinline__ void mma_bf16(float* c, const uint32_t* a, uint32_t b0, uint32_t b1){
    asm("mma.sync.aligned.m16n8k16.row.col.f32.bf16.bf16.f32 "
        "{%0,%1,%2,%3},{%4,%5,%6,%7},{%8,%9},{%0,%1,%2,%3};"
        : "+f"(c[0]), "+f"(c[1]), "+f"(c[2]), "+f"(c[3])
        : "r"(a[0]), "r"(a[1]), "r"(a[2]), "r"(a[3]), "r"(b0), "r"(b1));
}
__device__ __forceinline__ void ldsm4t(uint32_t& r0, uint32_t& r1, uint32_t& r2, uint32_t& r3, uint32_t addr){
    asm volatile("ldmatrix.sync.aligned.m8n8.x4.trans.shared.b16 {%0,%1,%2,%3}, [%4];"
        : "=r"(r0), "=r"(r1), "=r"(r2), "=r"(r3) : "r"(addr) : "memory");
}

// one GEMM layer, half-n per warp: 16 o-rows x 12 n8-tiles, 3 compensation passes
__device__ __forceinline__ void layer_mma12(float acc[12][4],
    const __nv_bfloat16* Whi, const __nv_bfloat16* Wlo,
    uint32_t sbH, uint32_t sbL, int h, int mrow0,
    int qr, int rB, int chL, int key)
{
    #pragma unroll
    for (int i = 0; i < 12; i++){ acc[i][0]=0.f; acc[i][1]=0.f; acc[i][2]=0.f; acc[i][3]=0.f; }

    const int ca = (rB & 3)*2;   // A-fragment column offset (== (lane&3)*2)
    uint32_t af[8][4];
    {
        const __nv_bfloat16* pw = Whi + (mrow0 + qr)*128 + ca;
        #pragma unroll
        for (int kt = 0; kt < 8; kt++){
            af[kt][0] = *(const uint32_t*)(pw + kt*16);
            af[kt][1] = *(const uint32_t*)(pw + kt*16 + 1024);
            af[kt][2] = *(const uint32_t*)(pw + kt*16 + 8);
            af[kt][3] = *(const uint32_t*)(pw + kt*16 + 1032);
        }
    }
    #pragma unroll 1
    for (int pass = 0; pass < 3; pass++){
        if (pass == 2){
            const __nv_bfloat16* pw = Wlo + (mrow0 + qr)*128 + ca;
            #pragma unroll
            for (int kt = 0; kt < 8; kt++){
                af[kt][0] = *(const uint32_t*)(pw + kt*16);
                af[kt][1] = *(const uint32_t*)(pw + kt*16 + 1024);
                af[kt][2] = *(const uint32_t*)(pw + kt*16 + 8);
                af[kt][3] = *(const uint32_t*)(pw + kt*16 + 1032);
            }
        }
        const uint32_t rowbase = ((pass == 1) ? sbL : sbH) + (uint32_t)rB*ROWB;
        #pragma unroll
        for (int kt = 0; kt < 8; kt++){
            const uint32_t kb = rowbase + (uint32_t)kt*16*ROWB;
            #pragma unroll
            for (int d = 0; d < 3; d++){
                #pragma unroll
                for (int u = 0; u < 2; u++){
                    int chunk = d*8 + h*4 + 2*u + chL;
                    uint32_t addr = kb + ((uint32_t)(chunk ^ key) << 4);
                    uint32_t b0, b1, b2, b3;
                    ldsm4t(b0, b1, b2, b3, addr);
                    mma_bf16(acc[d*4 + 2*u],     af[kt], b0, b1);
                    mma_bf16(acc[d*4 + 2*u + 1], af[kt], b2, b3);
                }
            }
        }
    }
}

// epilogues: MODE 0 = bias+gate, 1 = LNA, 2 = raw copy. Writes split h back to images.
template<int MODE>
__device__ __forceinline__ void epi(float acc[12][4], char* sm, int o0, int h, int cb, int bbase)
{
    #pragma unroll
    for (int r = 0; r < 2; r++){
        const int o = o0 + r*8;
        const int keyo = o & 7;
        float b0=0.f, b1=0.f, b2=0.f, sv=0.f;
        if (MODE == 0){
            b0 = g_bias1[(bbase+o)*3+0]; b1 = g_bias1[(bbase+o)*3+1]; b2 = g_bias1[(bbase+o)*3+2];
            sv = g_s2v1[bbase+o];
        }
        #pragma unroll
        for (int lp = 0; lp < 4; lp++){
            const int pt = h*4 + lp;
            uint32_t offd[3];
            #pragma unroll
            for (int d = 0; d < 3; d++)
                offd[d] = (uint32_t)(o*ROWB + (((d*8+pt) ^ keyo) << 4) + cb*2);
            float x0 = acc[lp][2*r],    x1 = acc[lp][2*r+1];
            float y0 = acc[4+lp][2*r],  y1 = acc[4+lp][2*r+1];
            float z0 = acc[8+lp][2*r],  z1 = acc[8+lp][2*r+1];
            float h3[3][2];
            if (MODE == 0){
                float q00=x0+b0, q10=y0+b1, q20=z0+b2;
                float q01=x1+b0, q11=y1+b1, q21=z1+b2;
                float g0 = 1.0f + sv/(sqrtf(q00*q00+q10*q10+q20*q20)+EPSN);
                float g1 = 1.0f + sv/(sqrtf(q01*q01+q11*q11+q21*q21)+EPSN);
                h3[0][0]=q00*g0; h3[1][0]=q10*g0; h3[2][0]=q20*g0;
                h3[0][1]=q01*g1; h3[1][1]=q11*g1; h3[2][1]=q21*g1;
            } else if (MODE == 2){
                h3[0][0]=x0; h3[0][1]=x1; h3[1][0]=y0; h3[1][1]=y1; h3[2][0]=z0; h3[2][1]=z1;
            } else {
                float q[3][2];
                #pragma unroll
                for (int d = 0; d < 3; d++){
                    uint32_t qh = *(uint32_t*)(sm + offd[d]);
                    uint32_t ql = *(uint32_t*)(sm + IMG + offd[d]);
                    q[d][0] = bl(qh)+bl(ql); q[d][1] = bhf(qh)+bhf(ql);
                }
                float inv0 = 1.0f/(sqrtf(x0*x0+y0*y0+z0*z0)+EPSN);
                float mf0  = fminf((q[0][0]*x0+q[1][0]*y0+q[2][0]*z0)*inv0, 0.0f)*inv0;
                float inv1 = 1.0f/(sqrtf(x1*x1+y1*y1+z1*z1)+EPSN);
                float mf1  = fminf((q[0][1]*x1+q[1][1]*y1+q[2][1]*z1)*inv1, 0.0f)*inv1;
                h3[0][0]=q[0][0]-mf0*x0; h3[1][0]=q[1][0]-mf0*y0; h3[2][0]=q[2][0]-mf0*z0;
                h3[0][1]=q[0][1]-mf1*x1; h3[1][1]=q[1][1]-mf1*y1; h3[2][1]=q[2][1]-mf1*z1;
            }
            #pragma unroll
            for (int d = 0; d < 3; d++){
                uint32_t hw = pk_bf(h3[d][0], h3[d][1]);
                uint32_t lw = pk_bf(h3[d][0]-bl(hw), h3[d][1]-bhf(hw));
                *(uint32_t*)(sm + offd[d])       = hw;
                *(uint32_t*)(sm + IMG + offd[d]) = lw;
            }
        }
    }
}

// ---------------- main kernel ----------------
__global__ void __launch_bounds__(512, 1)
main_mma(const float* __restrict__ pf, const float* __restrict__ scale,
         const float* __restrict__ center, float* __restrict__ out)
{
    extern __shared__ char sm[];
    const uint32_t sbH = smem_u32(sm), sbL = sbH + IMG;
    const int tid = threadIdx.x, w = tid >> 5, lane = tid & 31;
    const int b = blockIdx.y, m0 = blockIdx.x * 64;
    const int og = w >> 1, h = w & 1;
    const int qr = lane >> 2, cb = (lane & 3)*2;
    const int rB = lane & 15, chL = lane >> 4, key = rB & 7;

    // build hi/lo activation images from point_feat: row = channel c, col n = d*64+p
    #pragma unroll 1
    for (int it = 0; it < 12; it++){
        int idx = tid + it*512;
        int seg = idx & 15, d = (idx >> 4) % 3, c = idx / 48;
        float4 v = __ldg((const float4*)(pf + (((size_t)(b*128+c)*3+d)*NM + m0 + seg*4)));
        int n0 = d*64 + seg*4;
        uint32_t off = (uint32_t)(c*ROWB + (((n0>>3) ^ (c&7)) << 4) + (n0&7)*2);
        uint32_t h01 = pk_bf(v.x, v.y), h23 = pk_bf(v.z, v.w);
        uint32_t l01 = pk_bf(v.x - bl(h01), v.y - bhf(h01));
        uint32_t l23 = pk_bf(v.z - bl(h23), v.w - bhf(h23));
        *(uint32_t*)(sm + off)           = h01;
        *(uint32_t*)(sm + off + 4)       = h23;
        *(uint32_t*)(sm + IMG + off)     = l01;
        *(uint32_t*)(sm + IMG + off + 4) = l23;
    }
    __syncthreads();

    float acc[12][4];
    const int o0 = og*16 + qr;
    const int bbase = b*128;

    layer_mma12(acc, g_Whi[0], g_Wlo[0], sbH, sbL, h, og*16, qr, rB, chL, key);
    __syncthreads();
    epi<0>(acc, sm, o0, h, cb, bbase);
    __syncthreads();

    layer_mma12(acc, g_Whi[1], g_Wlo[1], sbH, sbL, h, og*16, qr, rB, chL, key);
    __syncthreads();
    epi<1>(acc, sm, o0, h, cb, bbase);
    __syncthreads();

    layer_mma12(acc, g_Whi[2], g_Wlo[2], sbH, sbL, h, og*16, qr, rB, chL, key);
    __syncthreads();
    epi<2>(acc, sm, o0, h, cb, bbase);
    __syncthreads();

    layer_mma12(acc, g_Whi[3], g_Wlo[3], sbH, sbL, h, og*16, qr, rB, chL, key);
    __syncthreads();
    epi<1>(acc, sm, o0, h, cb, bbase);
    __syncthreads();

    // final projection: rows 0-1 of a 16-row tile; only og==0 warps participate
    if (og == 0){
        layer_mma12(acc, g_Whi[4], g_Wlo[4], sbH, sbL, h, 0, qr, rB, chL, key);
        if (lane < 8){
            const float sc = __ldg(scale + b);
            const int o2 = qr;   // 0 or 1
            #pragma unroll
            for (int d = 0; d < 3; d++){
                #pragma unroll
                for (int lp = 0; lp < 4; lp++){
                    const int pt = h*4 + lp;
                    #pragma unroll
                    for (int j = 0; j < 2; j++){
                        int p = pt*8 + cb + j;
                        float v = acc[d*4+lp][j];
                        if (o2 == 0) v = v*sc + __ldg(center + b*3 + d);
                        out[((size_t)b*NM + m0 + p)*6 + o2*3 + d] = v;
                    }
                }
            }
        }
    }
}

// ---------------- weight split images ----------------
__global__ void buildW_k(const float* __restrict__ W1x, const float* __restrict__ W1xd,
                         const float* __restrict__ W2x, const float* __restrict__ W2xd,
                         const float* __restrict__ W3x)
{
    const int m = blockIdx.x;
    for (int i = threadIdx.x; i < 16384; i += 256){
        int o = i >> 7, k = i & 127;
        float w = (m==0) ? W1x[o*136+k] : (m==1) ? W1xd[o*128+k] : (m==2) ? W2x[o*128+k]
                : (m==3) ? W2xd[o*128+k] : ((o<2) ? W3x[o*128+k] : 0.0f);
        __nv_bfloat16 h = __float2bfloat16(w);
        g_Whi[m][i] = h;
        g_Wlo[m][i] = __float2bfloat16(w - __bfloat162float(h));
    }
}

// ---------------- prep: bias/s2v + gripper branch (fp32) ----------------
__global__ void prep_k(const float* __restrict__ z_pos, const float* __restrict__ z_dir,
                       const float* __restrict__ z_scalar, const float* __restrict__ gfeat,
                       const float* __restrict__ center, const float* __restrict__ scale,
                       const float* __restrict__ W1x, const float* __restrict__ W1x_s,
                       const float* __restrict__ W1g, const float* __restrict__ W1g_d,
                       const float* __restrict__ W1g_s, const float* __restrict__ W2g,
                       const float* __restrict__ W2g_d, const float* __restrict__ Wg_vs,
                       float* __restrict__ out)
{
    __shared__ float vg[136*3], bq[128*3], bhm[128*3], nh[128], zs[8*3];
    const int b = blockIdx.x, o = threadIdx.x;
    if (o < 24){
        int r = o/3, d = o%3;
        float v = (r < 2) ? (z_pos[(b*2+r)*3+d] - center[b*3+d]) / scale[b] : z_dir[(b*6+(r-2))*3+d];
        zs[r*3+d] = v;
        if (r < 2) g_zposn[(b*2+r)*3+d] = v;
    }
    __syncthreads();
    {
        g_s2v1[b*128+o] = W1x_s[o*2]*z_scalar[b*2] + W1x_s[o*2+1]*z_scalar[b*2+1];
        #pragma unroll
        for (int d = 0; d < 3; d++){
            float s = 0.0f;
            #pragma unroll
            for (int k = 0; k < 8; k++) s += W1x[o*136 + 128 + k] * zs[k*3+d];
            g_bias1[(b*128+o)*3+d] = s;
        }
    }
    for (int i = o; i < 408; i += 128){
        int c = i/3, d = i%3;
        vg[i] = (c < 128) ? gfeat[(b*128+c)*3+d] : zs[(c-128)*3+d];
    }
    __syncthreads();
    float q[3], dv[3];
    #pragma unroll
    for (int d = 0; d < 3; d++){ float s=0; for (int c=0;c<136;c++) s += W1g[o*136+c]*vg[c*3+d]; q[d]=s; }
    {
        float sg = W1g_s[o*2]*z_scalar[b*2] + W1g_s[o*2+1]*z_scalar[b*2+1];
        float g = 1.0f + sg/(sqrtf(q[0]*q[0]+q[1]*q[1]+q[2]*q[2])+EPSN);
        q[0]*=g; q[1]*=g; q[2]*=g;
    }
    bq[o*3]=q[0]; bq[o*3+1]=q[1]; bq[o*3+2]=q[2];
    __syncthreads();
    #pragma unroll
    for (int d = 0; d < 3; d++){ float s=0; for (int c=0;c<128;c++) s += W1g_d[o*128+c]*bq[c*3+d]; dv[d]=s; }
    {
        float inv = 1.0f/(sqrtf(dv[0]*dv[0]+dv[1]*dv[1]+dv[2]*dv[2]) + EPSN);
        float mf = fminf((q[0]*dv[0]+q[1]*dv[1]+q[2]*dv[2])*inv, 0.0f)*inv;
        q[0]-=mf*dv[0]; q[1]-=mf*dv[1]; q[2]-=mf*dv[2];
    }
    bhm[o*3]=q[0]; bhm[o*3+1]=q[1]; bhm[o*3+2]=q[2];
    __syncthreads();
    #pragma unroll
    for (int d = 0; d < 3; d++){ float s=0; for (int c=0;c<128;c++) s += W2g[o*128+c]*bhm[c*3+d]; q[d]=s; }
    bq[o*3]=q[0]; bq[o*3+1]=q[1]; bq[o*3+2]=q[2];
    __syncthreads();
    #pragma unroll
    for (int d = 0; d < 3; d++){ float s=0; for (int c=0;c<128;c++) s += W2g_d[o*128+c]*bq[c*3+d]; dv[d]=s; }
    {
        float inv = 1.0f/(sqrtf(dv[0]*dv[0]+dv[1]*dv[1]+dv[2]*dv[2]) + EPSN);
        float mf = fminf((q[0]*dv[0]+q[1]*dv[1]+q[2]*dv[2])*inv, 0.0f)*inv;
        q[0]-=mf*dv[0]; q[1]-=mf*dv[1]; q[2]-=mf*dv[2];
    }
    nh[o] = sqrtf(q[0]*q[0]+q[1]*q[1]+q[2]*q[2]);
    __syncthreads();
    if (o < 2){
        float s = 0; for (int c = 0; c < 128; c++) s += Wg_vs[o*128+c]*nh[c];
        float gr = 1.0f/(1.0f+expf(-s));
        g_grip[b*2+o] = gr;
        out[GRIP_OFF + b*2+o] = gr;
    }
}

__global__ void argmin_k(const float* __restrict__ pc)
{
    __shared__ float sv[256]; __shared__ int si[256];
    const int be = blockIdx.x, b = be >> 1;
    const float zx = g_zposn[be*3], zy = g_zposn[be*3+1], zz = g_zposn[be*3+2];
    const float* p = pc + (size_t)b*NM*3;
    float best = 3.4e38f; int bi = 0;
    for (int m = threadIdx.x; m < NM; m += blockDim.x){
        float dx=zx-p[m*3], dy=zy-p[m*3+1], dz=zz-p[m*3+2];
        float d = sqrtf(dx*dx+dy*dy+dz*dz);
        if (d < best){ best = d; bi = m; }
    }
    sv[threadIdx.x]=best; si[threadIdx.x]=bi;
    __syncthreads();
    for (int s = 128; s > 0; s >>= 1){
        if (threadIdx.x < s){
            float ov = sv[threadIdx.x+s]; int oi = si[threadIdx.x+s];
            if (ov < sv[threadIdx.x] || (ov == sv[threadIdx.x] && oi < si[threadIdx.x])){
                sv[threadIdx.x]=ov; si[threadIdx.x]=oi;
            }
        }
        __syncthreads();
    }
    if (threadIdx.x == 0) g_closest[be] = si[0];
}

__global__ void assemble_k(float* __restrict__ out)
{
    const int t = threadIdx.x;
    if (t < 112){
        int b = t/14, j = t%14, e = j/7, r = j%7;
        float v;
        if (r == 0) v = g_grip[b*2+e];
        else { int m = g_closest[b*2+e]; v = out[((size_t)b*NM+m)*6 + (r-1)]; }
        out[AC_OFF + t] = v;
    }
}

// ---------------- launch ----------------
extern "C" void kernel_launch(void* const* d_in, const int* in_sizes, int n_in,
                              void* d_out, int out_size)
{
    const float* pc        = (const float*)d_in[0];
    const float* z_pos     = (const float*)d_in[1];
    const float* z_dir     = (const float*)d_in[2];
    const float* z_scalar  = (const float*)d_in[3];
    const float* point_feat= (const float*)d_in[4];
    const float* gfeat     = (const float*)d_in[5];
    const float* center    = (const float*)d_in[6];
    const float* scale     = (const float*)d_in[7];
    const float* W1x       = (const float*)d_in[8];
    const float* W1x_d     = (const float*)d_in[9];
    const float* W1x_s     = (const float*)d_in[10];
    const float* W2x       = (const float*)d_in[11];
    const float* W2x_d     = (const float*)d_in[12];
    const float* W3x       = (const float*)d_in[13];
    const float* W1g       = (const float*)d_in[14];
    const float* W1g_d     = (const float*)d_in[15];
    const float* W1g_s     = (const float*)d_in[16];
    const float* W2g       = (const float*)d_in[17];
    const float* W2g_d     = (const float*)d_in[18];
    const float* Wg_vs     = (const float*)d_in[19];
    float* out = (float*)d_out;

    cudaFuncSetAttribute(main_mma, cudaFuncAttributeMaxDynamicSharedMemorySize, 2*IMG);

    buildW_k<<<5, 256>>>(W1x, W1x_d, W2x, W2x_d, W3x);
    prep_k<<<NB, 128>>>(z_pos, z_dir, z_scalar, gfeat, center, scale,
                        W1x, W1x_s, W1g, W1g_d, W1g_s, W2g, W2g_d, Wg_vs, out);
    argmin_k<<<16, 256>>>(pc);
    main_mma<<<dim3(NM/64, NB), 512, 2*IMG>>>(point_feat, scale, center, out);
    assemble_k<<<1, 128>>>(out);
}